// round 6
// baseline (speedup 1.0000x reference)
#include <cuda_runtime.h>
#include <cuda_fp16.h>
#include <cstdint>
#include <mma.h>
using namespace nvcuda;

#define B_SZ    4
#define L_SZ    1024
#define DM      1024
#define EI      2048
#define NS      16
#define DTR     64
#define MR      (B_SZ * L_SZ)          // 4096 token rows

// ---------------- scratch (static device globals; no allocation) ----------------
__device__ __half g_xh   [MR * DM];        // rmsnorm output, fp16
__device__ __half g_WinH [DM * 2 * EI];    // W_in fp16
__device__ __half g_WoutH[EI * DM];        // W_out fp16
__device__ float  g_xz   [MR * 2 * EI];    // in-proj output (x_in | z)
__device__ float  g_xact [MR * EI];        // silu(conv(x_in)) fp32
__device__ float  g_xdb  [MR * 96];        // [dt(64) | B(16) | C(16)]
__device__ float  g_delta[MR * EI];        // softplus(dt@W_dt + b_dt)
__device__ __half g_ygH  [MR * EI];        // y * silu(z), fp16
__device__ float  g_outtmp[MR * DM];       // y_g @ W_out

// ---------------- rmsnorm -> fp16 ----------------
__global__ void rmsnorm_kernel(const float* __restrict__ hs,
                               const float* __restrict__ w) {
    int row = blockIdx.x;
    const float4* hrow = (const float4*)(hs + (size_t)row * DM);
    float4 v = hrow[threadIdx.x];                 // 256 thr * 4 = 1024
    float ss = v.x*v.x + v.y*v.y + v.z*v.z + v.w*v.w;
    #pragma unroll
    for (int o = 16; o; o >>= 1) ss += __shfl_xor_sync(~0u, ss, o);
    __shared__ float sred[8];
    int warp = threadIdx.x >> 5, lane = threadIdx.x & 31;
    if (lane == 0) sred[warp] = ss;
    __syncthreads();
    if (warp == 0) {
        float s = lane < 8 ? sred[lane] : 0.f;
        #pragma unroll
        for (int o = 4; o; o >>= 1) s += __shfl_xor_sync(~0u, s, o);
        if (lane == 0) sred[0] = rsqrtf(s / (float)DM + 1e-6f);
    }
    __syncthreads();
    float sc = sred[0];
    float4 wl = ((const float4*)w)[threadIdx.x];
    __half2* out = (__half2*)(g_xh + (size_t)row * DM);
    out[threadIdx.x * 2]     = __floats2half2_rn(v.x * sc * wl.x, v.y * sc * wl.y);
    out[threadIdx.x * 2 + 1] = __floats2half2_rn(v.z * sc * wl.z, v.w * sc * wl.w);
}

// ---------------- f32 -> f16 convert (half2 granularity) ----------------
__global__ void f2h_kernel(const float* __restrict__ src, __half* __restrict__ dst, int n2) {
    int i = blockIdx.x * blockDim.x + threadIdx.x;
    if (i < n2) {
        float2 v = ((const float2*)src)[i];
        ((__half2*)dst)[i] = __floats2half2_rn(v.x, v.y);
    }
}

// ---------------- cp.async helper ----------------
__device__ __forceinline__ void cp16(void* s, const void* g) {
    unsigned int sa = (unsigned int)__cvta_generic_to_shared(s);
    asm volatile("cp.async.cg.shared.global [%0], [%1], 16;\n" :: "r"(sa), "l"(g));
}
__device__ __forceinline__ void cp_commit() {
    asm volatile("cp.async.commit_group;\n" ::: "memory");
}
__device__ __forceinline__ void cp_wait1() {
    asm volatile("cp.async.wait_group 1;\n" ::: "memory");
}

// ---------------- fp16 WMMA GEMM, 2-stage cp.async pipeline ----------------
// C(MxN,f32) = A(MxK) @ B(KxN), all row-major. BM=128, BN=128, BK=32.
#define GBM 128
#define GBN 128
#define GBK 32
#define AS_LD 40     // 32 + 8 halves pad (80B rows, 16B aligned)
#define BS_LD 136    // 128 + 8 halves pad (272B rows, 16B aligned)

__global__ void __launch_bounds__(256) gemm_h_kernel(const __half* __restrict__ A,
                                                     const __half* __restrict__ Bm,
                                                     float* __restrict__ C,
                                                     int M, int N, int K) {
    __shared__ __half As[2][GBM * AS_LD];
    __shared__ __half Bs[2][GBK * BS_LD];
    int bm = blockIdx.y * GBM, bn = blockIdx.x * GBN;
    int wid = threadIdx.x >> 5;
    int wm = wid >> 2, wn = wid & 3;   // 2x4 warp grid, warp tile 64x32

    wmma::fragment<wmma::accumulator, 16, 16, 16, float> acc[4][2];
    #pragma unroll
    for (int i = 0; i < 4; i++)
        #pragma unroll
        for (int j = 0; j < 2; j++) wmma::fill_fragment(acc[i][j], 0.f);

    int tiles = K / GBK;

    // async load of one k-tile into buffer `buf`
    auto load_stage = [&](int t, int buf) {
        int k0 = t * GBK;
        #pragma unroll
        for (int r = 0; r < 2; r++) {               // As: 128x32 halves = 512 uint4
            int idx = threadIdx.x + r * 256;
            int row = idx >> 2, cg = idx & 3;
            cp16(&As[buf][row * AS_LD + cg * 8],
                 &A[(size_t)(bm + row) * K + k0 + cg * 8]);
        }
        #pragma unroll
        for (int r = 0; r < 2; r++) {               // Bs: 32x128 halves = 512 uint4
            int idx = threadIdx.x + r * 256;
            int row = idx >> 4, cg = idx & 15;
            cp16(&Bs[buf][row * BS_LD + cg * 8],
                 &Bm[(size_t)(k0 + row) * N + bn + cg * 8]);
        }
    };

    load_stage(0, 0);
    cp_commit();

    for (int t = 0; t < tiles; t++) {
        int cur = t & 1;
        if (t + 1 < tiles) load_stage(t + 1, (t + 1) & 1);
        cp_commit();
        cp_wait1();              // tile t resident
        __syncthreads();

        #pragma unroll
        for (int kk = 0; kk < GBK; kk += 16) {
            wmma::fragment<wmma::matrix_a, 16, 16, 16, __half, wmma::row_major> af[4];
            wmma::fragment<wmma::matrix_b, 16, 16, 16, __half, wmma::row_major> bf[2];
            #pragma unroll
            for (int i = 0; i < 4; i++)
                wmma::load_matrix_sync(af[i], &As[cur][(wm * 64 + i * 16) * AS_LD + kk], AS_LD);
            #pragma unroll
            for (int j = 0; j < 2; j++)
                wmma::load_matrix_sync(bf[j], &Bs[cur][kk * BS_LD + wn * 32 + j * 16], BS_LD);
            #pragma unroll
            for (int i = 0; i < 4; i++)
                #pragma unroll
                for (int j = 0; j < 2; j++)
                    wmma::mma_sync(acc[i][j], af[i], bf[j], acc[i][j]);
        }
        __syncthreads();         // protect cur buffer before it is overwritten
    }
    #pragma unroll
    for (int i = 0; i < 4; i++)
        #pragma unroll
        for (int j = 0; j < 2; j++)
            wmma::store_matrix_sync(&C[(size_t)(bm + wm * 64 + i * 16) * N + bn + wn * 32 + j * 16],
                                    acc[i][j], N, wmma::mem_row_major);
}

// ---------------- causal depthwise conv (K=4) + SiLU ----------------
__global__ void conv_silu_kernel(const float* __restrict__ cw) {
    int idx = blockIdx.x * blockDim.x + threadIdx.x;
    if (idx >= MR * EI) return;
    int e = idx & (EI - 1);
    int m = idx >> 11;
    int t = m & (L_SZ - 1);
    float w0 = cw[e * 4 + 0], w1 = cw[e * 4 + 1], w2 = cw[e * 4 + 2], w3 = cw[e * 4 + 3];
    float acc = w3 * g_xz[(size_t)m * (2 * EI) + e];
    if (t >= 1) acc += w2 * g_xz[(size_t)(m - 1) * (2 * EI) + e];
    if (t >= 2) acc += w1 * g_xz[(size_t)(m - 2) * (2 * EI) + e];
    if (t >= 3) acc += w0 * g_xz[(size_t)(m - 3) * (2 * EI) + e];
    float s = acc / (1.f + __expf(-acc));
    g_xact[idx] = s;
}

// ---------------- x_db = x_act(4096x2048) @ W_x(2048x96), fp32 SIMT ----------------
__global__ void __launch_bounds__(256) gemm_xdb_kernel(const float* __restrict__ Wx) {
    __shared__ float As[32 * 65];
    __shared__ float Ws[64 * 96];
    int m0 = blockIdx.x * 32;
    int r  = threadIdx.x & 31;
    int cg = threadIdx.x >> 5;            // 0..7 -> cols cg*12
    float acc[12];
    #pragma unroll
    for (int j = 0; j < 12; j++) acc[j] = 0.f;

    for (int k0 = 0; k0 < EI; k0 += 64) {
        #pragma unroll
        for (int i = 0; i < 2; i++) {     // As: 32x64 floats = 512 float4
            int idx = threadIdx.x + i * 256;
            int row = idx >> 4, c = (idx & 15) * 4;
            float4 v = *(const float4*)&g_xact[(size_t)(m0 + row) * EI + k0 + c];
            As[row * 65 + c] = v.x; As[row * 65 + c + 1] = v.y;
            As[row * 65 + c + 2] = v.z; As[row * 65 + c + 3] = v.w;
        }
        #pragma unroll
        for (int i = 0; i < 6; i++) {     // Ws: 64x96 floats = 1536 float4
            int idx = threadIdx.x + i * 256;
            int row = idx / 24, c = (idx % 24) * 4;
            *(float4*)&Ws[row * 96 + c] = *(const float4*)&Wx[(size_t)(k0 + row) * 96 + c];
        }
        __syncthreads();
        #pragma unroll 8
        for (int k = 0; k < 64; k++) {
            float a = As[r * 65 + k];
            #pragma unroll
            for (int j = 0; j < 12; j++)
                acc[j] = fmaf(a, Ws[k * 96 + cg * 12 + j], acc[j]);
        }
        __syncthreads();
    }
    #pragma unroll
    for (int j = 0; j < 12; j++)
        g_xdb[(size_t)(m0 + r) * 96 + cg * 12 + j] = acc[j];
}

// ---------------- delta = softplus(dt_lr(4096x64) @ W_dt(64x2048) + b_dt) ----------------
__global__ void __launch_bounds__(256) delta_kernel(const float* __restrict__ Wdt,
                                                    const float* __restrict__ bdt) {
    __shared__ float sdt[16 * 64];
    int m0 = (blockIdx.x >> 3) * 16;          // 256 row blocks
    int c0 = (blockIdx.x & 7) * 256;          // 8 col blocks
    for (int i = threadIdx.x; i < 16 * 64; i += 256) {
        int rr = i >> 6, kk = i & 63;
        sdt[i] = g_xdb[(size_t)(m0 + rr) * 96 + kk];
    }
    __syncthreads();
    int c = c0 + threadIdx.x;
    float acc[16];
    #pragma unroll
    for (int r = 0; r < 16; r++) acc[r] = 0.f;
    #pragma unroll 4
    for (int k = 0; k < 64; k++) {
        float w = Wdt[(size_t)k * EI + c];
        #pragma unroll
        for (int r = 0; r < 16; r++)
            acc[r] = fmaf(sdt[r * 64 + k], w, acc[r]);
    }
    float bb = bdt[c];
    #pragma unroll
    for (int r = 0; r < 16; r++) {
        float v = acc[r] + bb;
        float sp = (v > 20.f) ? v : log1pf(__expf(v));
        g_delta[(size_t)(m0 + r) * EI + c] = sp;
    }
}

// ---------------- selective scan (+ fused output gate y*silu(z)) ----------------
// 4 lanes per channel, 4 states per lane; depth-1 register prefetch.
__global__ void __launch_bounds__(128) scan_kernel(const float* __restrict__ A_log,
                                                   const float* __restrict__ Dp,
                                                   float* __restrict__ hlast_out) {
    int b  = blockIdx.x >> 6;                 // grid 256 = 4 batches * 64 groups
    int e0 = (blockIdx.x & 63) * 32;
    int lane = threadIdx.x & 31;
    int w    = threadIdx.x >> 5;
    int ch   = w * 8 + (lane >> 2);           // 8 channels per warp
    int e    = e0 + ch;
    int q    = (lane & 3) * 4;                // state offset 0/4/8/12
    float Aa[4], h[4];
    #pragma unroll
    for (int j = 0; j < 4; j++) {
        Aa[j] = -__expf(A_log[e * NS + q + j]);
        h[j] = 0.f;
    }
    float Dpar = Dp[e];
    int mbase = b * L_SZ;
    bool wlane = ((lane & 3) == 0);

    float  d0 = g_delta[(size_t)mbase * EI + e];
    float  u0 = g_xact [(size_t)mbase * EI + e];
    float4 B0 = *(const float4*)&g_xdb[(size_t)mbase * 96 + 64 + q];
    float4 C0 = *(const float4*)&g_xdb[(size_t)mbase * 96 + 80 + q];

    for (int t = 0; t < L_SZ; t++) {
        float d1 = 0.f, u1 = 0.f; float4 B1 = B0, C1 = C0;
        if (t + 1 < L_SZ) {
            size_t m1 = (size_t)(mbase + t + 1);
            d1 = g_delta[m1 * EI + e];
            u1 = g_xact [m1 * EI + e];
            B1 = *(const float4*)&g_xdb[m1 * 96 + 64 + q];
            C1 = *(const float4*)&g_xdb[m1 * 96 + 80 + q];
        }
        float du = d0 * u0;
        float dA0 = __expf(d0 * Aa[0]);
        float dA1 = __expf(d0 * Aa[1]);
        float dA2 = __expf(d0 * Aa[2]);
        float dA3 = __expf(d0 * Aa[3]);
        h[0] = fmaf(dA0, h[0], du * B0.x);
        h[1] = fmaf(dA1, h[1], du * B0.y);
        h[2] = fmaf(dA2, h[2], du * B0.z);
        h[3] = fmaf(dA3, h[3], du * B0.w);
        float yp = h[0]*C0.x + h[1]*C0.y + h[2]*C0.z + h[3]*C0.w;
        yp += __shfl_xor_sync(~0u, yp, 1);
        yp += __shfl_xor_sync(~0u, yp, 2);
        if (wlane) {
            // fused gate: y * silu(z)
            float z  = g_xz[(size_t)(mbase + t) * (2 * EI) + EI + e];
            float zg = z / (1.f + __expf(-z));
            g_ygH[(size_t)(mbase + t) * EI + e] =
                __float2half((yp + u0 * Dpar) * zg);
        }
        d0 = d1; u0 = u1; B0 = B1; C0 = C1;
    }
    *(float4*)&hlast_out[((size_t)b * EI + e) * NS + q] = make_float4(h[0], h[1], h[2], h[3]);
}

// ---------------- residual add ----------------
__global__ void resadd_kernel(const float* __restrict__ hs, float* __restrict__ out) {
    int i = blockIdx.x * blockDim.x + threadIdx.x;
    if (i < MR * DM) out[i] = g_outtmp[i] + hs[i];
}

// ---------------- launch ----------------
extern "C" void kernel_launch(void* const* d_in, const int* in_sizes, int n_in,
                              void* d_out, int out_size) {
    const float* hs     = (const float*)d_in[0];
    const float* norm_w = (const float*)d_in[1];
    const float* W_in   = (const float*)d_in[2];
    const float* conv_w = (const float*)d_in[3];
    const float* W_x    = (const float*)d_in[4];
    const float* W_dt   = (const float*)d_in[5];
    const float* b_dt   = (const float*)d_in[6];
    const float* A_log  = (const float*)d_in[7];
    const float* D_par  = (const float*)d_in[8];
    const float* W_out  = (const float*)d_in[9];
    float* out   = (float*)d_out;
    float* hlast = out + (size_t)MR * DM;

    void *p_xh, *p_WinH, *p_WoutH, *p_xz, *p_ygH, *p_outtmp;
    cudaGetSymbolAddress(&p_xh, g_xh);
    cudaGetSymbolAddress(&p_WinH, g_WinH);
    cudaGetSymbolAddress(&p_WoutH, g_WoutH);
    cudaGetSymbolAddress(&p_xz, g_xz);
    cudaGetSymbolAddress(&p_ygH, g_ygH);
    cudaGetSymbolAddress(&p_outtmp, g_outtmp);

    rmsnorm_kernel<<<MR, 256>>>(hs, norm_w);
    {
        int n2 = DM * 2 * EI / 2;
        f2h_kernel<<<(n2 + 255) / 256, 256>>>(W_in, (__half*)p_WinH, n2);
    }
    {
        int n2 = EI * DM / 2;
        f2h_kernel<<<(n2 + 255) / 256, 256>>>(W_out, (__half*)p_WoutH, n2);
    }
    // xz = x @ W_in : M=4096, N=4096, K=1024
    gemm_h_kernel<<<dim3(2 * EI / GBN, MR / GBM), 256>>>(
        (const __half*)p_xh, (const __half*)p_WinH, (float*)p_xz, MR, 2 * EI, DM);
    conv_silu_kernel<<<MR * EI / 256, 256>>>(conv_w);
    gemm_xdb_kernel<<<MR / 32, 256>>>(W_x);
    delta_kernel<<<(MR / 16) * (EI / 256), 256>>>(W_dt, b_dt);
    scan_kernel<<<256, 128>>>(A_log, D_par, hlast);
    // out_tmp = y_g @ W_out : M=4096, N=1024, K=2048
    gemm_h_kernel<<<dim3(DM / GBN, MR / GBM), 256>>>(
        (const __half*)p_ygH, (const __half*)p_WoutH, (float*)p_outtmp, MR, DM, EI);
    resadd_kernel<<<MR * DM / 256, 256>>>(hs, out);
}

// round 8
// speedup vs baseline: 1.0890x; 1.0890x over previous
#include <cuda_runtime.h>
#include <cuda_fp16.h>
#include <cstdint>
#include <mma.h>
using namespace nvcuda;

#define B_SZ    4
#define L_SZ    1024
#define DM      1024
#define EI      2048
#define NS      16
#define DTR     64
#define MR      (B_SZ * L_SZ)          // 4096 token rows

// ---------------- scratch (static device globals; no allocation) ----------------
__device__ __half g_xh   [MR * DM];        // rmsnorm output, fp16
__device__ __half g_WinH [DM * 2 * EI];    // W_in fp16
__device__ __half g_WoutH[EI * DM];        // W_out fp16
__device__ float  g_xz   [MR * 2 * EI];    // in-proj output (x_in | z)
__device__ float  g_xact [MR * EI];        // silu(conv(x_in)) fp32
__device__ float  g_xdb  [MR * 96];        // [dt(64) | B(16) | C(16)]
__device__ float  g_delta[MR * EI];        // softplus(dt@W_dt + b_dt)
__device__ __half g_ygH  [MR * EI];        // y * silu(z), fp16
__device__ float  g_outtmp[MR * DM];       // y_g @ W_out

// ---------------- rmsnorm -> fp16 ----------------
__global__ void rmsnorm_kernel(const float* __restrict__ hs,
                               const float* __restrict__ w) {
    int row = blockIdx.x;
    const float4* hrow = (const float4*)(hs + (size_t)row * DM);
    float4 v = hrow[threadIdx.x];                 // 256 thr * 4 = 1024
    float ss = v.x*v.x + v.y*v.y + v.z*v.z + v.w*v.w;
    #pragma unroll
    for (int o = 16; o; o >>= 1) ss += __shfl_xor_sync(~0u, ss, o);
    __shared__ float sred[8];
    int warp = threadIdx.x >> 5, lane = threadIdx.x & 31;
    if (lane == 0) sred[warp] = ss;
    __syncthreads();
    if (warp == 0) {
        float s = lane < 8 ? sred[lane] : 0.f;
        #pragma unroll
        for (int o = 4; o; o >>= 1) s += __shfl_xor_sync(~0u, s, o);
        if (lane == 0) sred[0] = rsqrtf(s / (float)DM + 1e-6f);
    }
    __syncthreads();
    float sc = sred[0];
    float4 wl = ((const float4*)w)[threadIdx.x];
    __half2* out = (__half2*)(g_xh + (size_t)row * DM);
    out[threadIdx.x * 2]     = __floats2half2_rn(v.x * sc * wl.x, v.y * sc * wl.y);
    out[threadIdx.x * 2 + 1] = __floats2half2_rn(v.z * sc * wl.z, v.w * sc * wl.w);
}

// ---------------- f32 -> f16 convert (half2 granularity) ----------------
__global__ void f2h_kernel(const float* __restrict__ src, __half* __restrict__ dst, int n2) {
    int i = blockIdx.x * blockDim.x + threadIdx.x;
    if (i < n2) {
        float2 v = ((const float2*)src)[i];
        ((__half2*)dst)[i] = __floats2half2_rn(v.x, v.y);
    }
}

// ---------------- cp.async helpers ----------------
__device__ __forceinline__ void cp16(void* s, const void* g) {
    unsigned int sa = (unsigned int)__cvta_generic_to_shared(s);
    asm volatile("cp.async.cg.shared.global [%0], [%1], 16;\n" :: "r"(sa), "l"(g));
}
__device__ __forceinline__ void cp_commit() {
    asm volatile("cp.async.commit_group;\n" ::: "memory");
}
__device__ __forceinline__ void cp_wait2() {
    asm volatile("cp.async.wait_group 2;\n" ::: "memory");
}

// ---------------- fp16 WMMA GEMM, 3-stage cp.async pipeline ----------------
// C(MxN,f32) = A(MxK) @ B(KxN), all row-major. BM=128, BN=128, BK=32.
#define GBM 128
#define GBN 128
#define GBK 32
#define NSTAGE 3
#define AS_LD 40     // 32 + 8 halves pad (80B rows, 16B aligned)
#define BS_LD 136    // 128 + 8 halves pad (272B rows, 16B aligned)

__global__ void __launch_bounds__(256) gemm_h_kernel(const __half* __restrict__ A,
                                                     const __half* __restrict__ Bm,
                                                     float* __restrict__ C,
                                                     int M, int N, int K) {
    __shared__ __half As[NSTAGE][GBM * AS_LD];
    __shared__ __half Bs[NSTAGE][GBK * BS_LD];
    int bm = blockIdx.y * GBM, bn = blockIdx.x * GBN;
    int wid = threadIdx.x >> 5;
    int wm = wid >> 2, wn = wid & 3;   // 2x4 warp grid, warp tile 64x32

    wmma::fragment<wmma::accumulator, 16, 16, 16, float> acc[4][2];
    #pragma unroll
    for (int i = 0; i < 4; i++)
        #pragma unroll
        for (int j = 0; j < 2; j++) wmma::fill_fragment(acc[i][j], 0.f);

    int tiles = K / GBK;

    auto load_stage = [&](int t, int buf) {
        int k0 = t * GBK;
        #pragma unroll
        for (int r = 0; r < 2; r++) {               // As: 128x32 halves = 512 uint4
            int idx = threadIdx.x + r * 256;
            int row = idx >> 2, cg = idx & 3;
            cp16(&As[buf][row * AS_LD + cg * 8],
                 &A[(size_t)(bm + row) * K + k0 + cg * 8]);
        }
        #pragma unroll
        for (int r = 0; r < 2; r++) {               // Bs: 32x128 halves = 512 uint4
            int idx = threadIdx.x + r * 256;
            int row = idx >> 4, cg = idx & 15;
            cp16(&Bs[buf][row * BS_LD + cg * 8],
                 &Bm[(size_t)(k0 + row) * N + bn + cg * 8]);
        }
    };

    // prologue: stages 0,1 in flight (each its own commit group)
    load_stage(0, 0); cp_commit();
    if (tiles > 1) { load_stage(1, 1); }
    cp_commit();

    for (int t = 0; t < tiles; t++) {
        int cur = t % NSTAGE;
        if (t + 2 < tiles) load_stage(t + 2, (t + 2) % NSTAGE);
        cp_commit();
        cp_wait2();              // tile t resident (<=2 younger groups pending)
        __syncthreads();

        #pragma unroll
        for (int kk = 0; kk < GBK; kk += 16) {
            wmma::fragment<wmma::matrix_a, 16, 16, 16, __half, wmma::row_major> af[4];
            wmma::fragment<wmma::matrix_b, 16, 16, 16, __half, wmma::row_major> bf[2];
            #pragma unroll
            for (int i = 0; i < 4; i++)
                wmma::load_matrix_sync(af[i], &As[cur][(wm * 64 + i * 16) * AS_LD + kk], AS_LD);
            #pragma unroll
            for (int j = 0; j < 2; j++)
                wmma::load_matrix_sync(bf[j], &Bs[cur][kk * BS_LD + wn * 32 + j * 16], BS_LD);
            #pragma unroll
            for (int i = 0; i < 4; i++)
                #pragma unroll
                for (int j = 0; j < 2; j++)
                    wmma::mma_sync(acc[i][j], af[i], bf[j], acc[i][j]);
        }
        __syncthreads();         // all warps done with `cur` before it is reloaded
    }
    #pragma unroll
    for (int i = 0; i < 4; i++)
        #pragma unroll
        for (int j = 0; j < 2; j++)
            wmma::store_matrix_sync(&C[(size_t)(bm + wm * 64 + i * 16) * N + bn + wn * 32 + j * 16],
                                    acc[i][j], N, wmma::mem_row_major);
}

// ---------------- causal depthwise conv (K=4) + SiLU ----------------
__global__ void conv_silu_kernel(const float* __restrict__ cw) {
    int idx = blockIdx.x * blockDim.x + threadIdx.x;
    if (idx >= MR * EI) return;
    int e = idx & (EI - 1);
    int m = idx >> 11;
    int t = m & (L_SZ - 1);
    float w0 = cw[e * 4 + 0], w1 = cw[e * 4 + 1], w2 = cw[e * 4 + 2], w3 = cw[e * 4 + 3];
    float acc = w3 * g_xz[(size_t)m * (2 * EI) + e];
    if (t >= 1) acc += w2 * g_xz[(size_t)(m - 1) * (2 * EI) + e];
    if (t >= 2) acc += w1 * g_xz[(size_t)(m - 2) * (2 * EI) + e];
    if (t >= 3) acc += w0 * g_xz[(size_t)(m - 3) * (2 * EI) + e];
    float s = acc / (1.f + __expf(-acc));
    g_xact[idx] = s;
}

// ---------------- x_db = x_act(4096x2048) @ W_x(2048x96), fp32 SIMT ----------------
__global__ void __launch_bounds__(256) gemm_xdb_kernel(const float* __restrict__ Wx) {
    __shared__ float As[32 * 65];
    __shared__ float Ws[64 * 96];
    int m0 = blockIdx.x * 32;
    int r  = threadIdx.x & 31;
    int cg = threadIdx.x >> 5;            // 0..7 -> cols cg*12
    float acc[12];
    #pragma unroll
    for (int j = 0; j < 12; j++) acc[j] = 0.f;

    for (int k0 = 0; k0 < EI; k0 += 64) {
        #pragma unroll
        for (int i = 0; i < 2; i++) {     // As: 32x64 floats = 512 float4
            int idx = threadIdx.x + i * 256;
            int row = idx >> 4, c = (idx & 15) * 4;
            float4 v = *(const float4*)&g_xact[(size_t)(m0 + row) * EI + k0 + c];
            As[row * 65 + c] = v.x; As[row * 65 + c + 1] = v.y;
            As[row * 65 + c + 2] = v.z; As[row * 65 + c + 3] = v.w;
        }
        #pragma unroll
        for (int i = 0; i < 6; i++) {     // Ws: 64x96 floats = 1536 float4
            int idx = threadIdx.x + i * 256;
            int row = idx / 24, c = (idx % 24) * 4;
            *(float4*)&Ws[row * 96 + c] = *(const float4*)&Wx[(size_t)(k0 + row) * 96 + c];
        }
        __syncthreads();
        #pragma unroll 8
        for (int k = 0; k < 64; k++) {
            float a = As[r * 65 + k];
            #pragma unroll
            for (int j = 0; j < 12; j++)
                acc[j] = fmaf(a, Ws[k * 96 + cg * 12 + j], acc[j]);
        }
        __syncthreads();
    }
    #pragma unroll
    for (int j = 0; j < 12; j++)
        g_xdb[(size_t)(m0 + r) * 96 + cg * 12 + j] = acc[j];
}

// ---------------- delta = softplus(dt_lr(4096x64) @ W_dt(64x2048) + b_dt) ----------------
__global__ void __launch_bounds__(256) delta_kernel(const float* __restrict__ Wdt,
                                                    const float* __restrict__ bdt) {
    __shared__ float sdt[16 * 64];
    int m0 = (blockIdx.x >> 3) * 16;          // 256 row blocks
    int c0 = (blockIdx.x & 7) * 256;          // 8 col blocks
    for (int i = threadIdx.x; i < 16 * 64; i += 256) {
        int rr = i >> 6, kk = i & 63;
        sdt[i] = g_xdb[(size_t)(m0 + rr) * 96 + kk];
    }
    __syncthreads();
    int c = c0 + threadIdx.x;
    float acc[16];
    #pragma unroll
    for (int r = 0; r < 16; r++) acc[r] = 0.f;
    #pragma unroll 4
    for (int k = 0; k < 64; k++) {
        float w = Wdt[(size_t)k * EI + c];
        #pragma unroll
        for (int r = 0; r < 16; r++)
            acc[r] = fmaf(sdt[r * 64 + k], w, acc[r]);
    }
    float bb = bdt[c];
    #pragma unroll
    for (int r = 0; r < 16; r++) {
        float v = acc[r] + bb;
        float sp = (v > 20.f) ? v : log1pf(__expf(v));
        g_delta[(size_t)(m0 + r) * EI + c] = sp;
    }
}

// ---------------- selective scan (+ fused output gate y*silu(z)) ----------------
// 4 lanes per channel, 4 states per lane; depth-1 register prefetch on ALL
// per-step operands (d, u, B, C, and the gate z).
__global__ void __launch_bounds__(128) scan_kernel(const float* __restrict__ A_log,
                                                   const float* __restrict__ Dp,
                                                   float* __restrict__ hlast_out) {
    int b  = blockIdx.x >> 6;                 // grid 256 = 4 batches * 64 groups
    int e0 = (blockIdx.x & 63) * 32;
    int lane = threadIdx.x & 31;
    int w    = threadIdx.x >> 5;
    int ch   = w * 8 + (lane >> 2);           // 8 channels per warp
    int e    = e0 + ch;
    int q    = (lane & 3) * 4;                // state offset 0/4/8/12
    float Aa[4], h[4];
    #pragma unroll
    for (int j = 0; j < 4; j++) {
        Aa[j] = -__expf(A_log[e * NS + q + j]);
        h[j] = 0.f;
    }
    float Dpar = Dp[e];
    int mbase = b * L_SZ;
    bool wlane = ((lane & 3) == 0);

    float  d0 = g_delta[(size_t)mbase * EI + e];
    float  u0 = g_xact [(size_t)mbase * EI + e];
    float  z0 = wlane ? g_xz[(size_t)mbase * (2 * EI) + EI + e] : 0.f;
    float4 B0 = *(const float4*)&g_xdb[(size_t)mbase * 96 + 64 + q];
    float4 C0 = *(const float4*)&g_xdb[(size_t)mbase * 96 + 80 + q];

    for (int t = 0; t < L_SZ; t++) {
        float d1 = 0.f, u1 = 0.f, z1 = 0.f; float4 B1 = B0, C1 = C0;
        if (t + 1 < L_SZ) {
            size_t m1 = (size_t)(mbase + t + 1);
            d1 = g_delta[m1 * EI + e];
            u1 = g_xact [m1 * EI + e];
            if (wlane) z1 = g_xz[m1 * (2 * EI) + EI + e];
            B1 = *(const float4*)&g_xdb[m1 * 96 + 64 + q];
            C1 = *(const float4*)&g_xdb[m1 * 96 + 80 + q];
        }
        float du = d0 * u0;
        float dA0 = __expf(d0 * Aa[0]);
        float dA1 = __expf(d0 * Aa[1]);
        float dA2 = __expf(d0 * Aa[2]);
        float dA3 = __expf(d0 * Aa[3]);
        h[0] = fmaf(dA0, h[0], du * B0.x);
        h[1] = fmaf(dA1, h[1], du * B0.y);
        h[2] = fmaf(dA2, h[2], du * B0.z);
        h[3] = fmaf(dA3, h[3], du * B0.w);
        float yp = h[0]*C0.x + h[1]*C0.y + h[2]*C0.z + h[3]*C0.w;
        yp += __shfl_xor_sync(~0u, yp, 1);
        yp += __shfl_xor_sync(~0u, yp, 2);
        if (wlane) {
            float zg = z0 / (1.f + __expf(-z0));     // silu(z)
            g_ygH[(size_t)(mbase + t) * EI + e] =
                __float2half((yp + u0 * Dpar) * zg);
        }
        d0 = d1; u0 = u1; z0 = z1; B0 = B1; C0 = C1;
    }
    *(float4*)&hlast_out[((size_t)b * EI + e) * NS + q] = make_float4(h[0], h[1], h[2], h[3]);
}

// ---------------- residual add ----------------
__global__ void resadd_kernel(const float* __restrict__ hs, float* __restrict__ out) {
    int i = blockIdx.x * blockDim.x + threadIdx.x;
    if (i < MR * DM) out[i] = g_outtmp[i] + hs[i];
}

// ---------------- launch ----------------
extern "C" void kernel_launch(void* const* d_in, const int* in_sizes, int n_in,
                              void* d_out, int out_size) {
    const float* hs     = (const float*)d_in[0];
    const float* norm_w = (const float*)d_in[1];
    const float* W_in   = (const float*)d_in[2];
    const float* conv_w = (const float*)d_in[3];
    const float* W_x    = (const float*)d_in[4];
    const float* W_dt   = (const float*)d_in[5];
    const float* b_dt   = (const float*)d_in[6];
    const float* A_log  = (const float*)d_in[7];
    const float* D_par  = (const float*)d_in[8];
    const float* W_out  = (const float*)d_in[9];
    float* out   = (float*)d_out;
    float* hlast = out + (size_t)MR * DM;

    void *p_xh, *p_WinH, *p_WoutH, *p_xz, *p_ygH, *p_outtmp;
    cudaGetSymbolAddress(&p_xh, g_xh);
    cudaGetSymbolAddress(&p_WinH, g_WinH);
    cudaGetSymbolAddress(&p_WoutH, g_WoutH);
    cudaGetSymbolAddress(&p_xz, g_xz);
    cudaGetSymbolAddress(&p_ygH, g_ygH);
    cudaGetSymbolAddress(&p_outtmp, g_outtmp);

    rmsnorm_kernel<<<MR, 256>>>(hs, norm_w);
    {
        int n2 = DM * 2 * EI / 2;
        f2h_kernel<<<(n2 + 255) / 256, 256>>>(W_in, (__half*)p_WinH, n2);
    }
    {
        int n2 = EI * DM / 2;
        f2h_kernel<<<(n2 + 255) / 256, 256>>>(W_out, (__half*)p_WoutH, n2);
    }
    // xz = x @ W_in : M=4096, N=4096, K=1024
    gemm_h_kernel<<<dim3(2 * EI / GBN, MR / GBM), 256>>>(
        (const __half*)p_xh, (const __half*)p_WinH, (float*)p_xz, MR, 2 * EI, DM);
    conv_silu_kernel<<<MR * EI / 256, 256>>>(conv_w);
    gemm_xdb_kernel<<<MR / 32, 256>>>(W_x);
    delta_kernel<<<(MR / 16) * (EI / 256), 256>>>(W_dt, b_dt);
    scan_kernel<<<256, 128>>>(A_log, D_par, hlast);
    // out_tmp = y_g @ W_out : M=4096, N=1024, K=2048
    gemm_h_kernel<<<dim3(DM / GBN, MR / GBM), 256>>>(
        (const __half*)p_ygH, (const __half*)p_WoutH, (float*)p_outtmp, MR, DM, EI);
    resadd_kernel<<<MR * DM / 256, 256>>>(hs, out);
}

// round 12
// speedup vs baseline: 1.8165x; 1.6681x over previous
#include <cuda_runtime.h>
#include <cuda_fp16.h>
#include <cstdint>
#include <mma.h>
using namespace nvcuda;

#define B_SZ    4
#define L_SZ    1024
#define DM      1024
#define EI      2048
#define NS      16
#define DTR     64
#define MR      (B_SZ * L_SZ)          // 4096 token rows

// ---------------- scratch (static device globals; no allocation) ----------------
__device__ __half g_xh   [MR * DM];        // rmsnorm output, fp16
__device__ __half g_WinH [DM * 2 * EI];    // W_in fp16
__device__ __half g_WoutH[EI * DM];        // W_out fp16
__device__ float  g_xz   [MR * 2 * EI];    // in-proj output (x_in | z)
__device__ float  g_xact [MR * EI];        // silu(conv(x_in)) fp32
__device__ float  g_xdb  [MR * 96];        // [dt(64) | B(16) | C(16)]
__device__ float  g_delta[MR * EI];        // softplus(dt@W_dt + b_dt)
__device__ __half g_ygH  [MR * EI];        // y * silu(z), fp16
__device__ float  g_outtmp[MR * DM];       // y_g @ W_out

// ---------------- rmsnorm -> fp16 ----------------
__global__ void rmsnorm_kernel(const float* __restrict__ hs,
                               const float* __restrict__ w) {
    int row = blockIdx.x;
    const float4* hrow = (const float4*)(hs + (size_t)row * DM);
    float4 v = hrow[threadIdx.x];                 // 256 thr * 4 = 1024
    float ss = v.x*v.x + v.y*v.y + v.z*v.z + v.w*v.w;
    #pragma unroll
    for (int o = 16; o; o >>= 1) ss += __shfl_xor_sync(~0u, ss, o);
    __shared__ float sred[8];
    int warp = threadIdx.x >> 5, lane = threadIdx.x & 31;
    if (lane == 0) sred[warp] = ss;
    __syncthreads();
    if (warp == 0) {
        float s = lane < 8 ? sred[lane] : 0.f;
        #pragma unroll
        for (int o = 4; o; o >>= 1) s += __shfl_xor_sync(~0u, s, o);
        if (lane == 0) sred[0] = rsqrtf(s / (float)DM + 1e-6f);
    }
    __syncthreads();
    float sc = sred[0];
    float4 wl = ((const float4*)w)[threadIdx.x];
    __half2* out = (__half2*)(g_xh + (size_t)row * DM);
    out[threadIdx.x * 2]     = __floats2half2_rn(v.x * sc * wl.x, v.y * sc * wl.y);
    out[threadIdx.x * 2 + 1] = __floats2half2_rn(v.z * sc * wl.z, v.w * sc * wl.w);
}

// ---------------- f32 -> f16 convert (half2 granularity) ----------------
__global__ void f2h_kernel(const float* __restrict__ src, __half* __restrict__ dst, int n2) {
    int i = blockIdx.x * blockDim.x + threadIdx.x;
    if (i < n2) {
        float2 v = ((const float2*)src)[i];
        ((__half2*)dst)[i] = __floats2half2_rn(v.x, v.y);
    }
}

// ---------------- cp.async helpers ----------------
__device__ __forceinline__ void cp16(void* s, const void* g) {
    unsigned int sa = (unsigned int)__cvta_generic_to_shared(s);
    asm volatile("cp.async.cg.shared.global [%0], [%1], 16;\n" :: "r"(sa), "l"(g));
}
__device__ __forceinline__ void cp_commit() {
    asm volatile("cp.async.commit_group;\n" ::: "memory");
}
__device__ __forceinline__ void cp_wait1() {
    asm volatile("cp.async.wait_group 1;\n" ::: "memory");
}
__device__ __forceinline__ void cp_wait2() {
    asm volatile("cp.async.wait_group 2;\n" ::: "memory");
}

// ---------------- fp16 WMMA GEMM, 3-stage cp.async pipeline ----------------
#define GBM 128
#define GBN 128
#define GBK 32
#define NSTAGE 3
#define AS_LD 40
#define BS_LD 136

__global__ void __launch_bounds__(256) gemm_h_kernel(const __half* __restrict__ A,
                                                     const __half* __restrict__ Bm,
                                                     float* __restrict__ C,
                                                     int M, int N, int K) {
    __shared__ __half As[NSTAGE][GBM * AS_LD];
    __shared__ __half Bs[NSTAGE][GBK * BS_LD];
    int bm = blockIdx.y * GBM, bn = blockIdx.x * GBN;
    int wid = threadIdx.x >> 5;
    int wm = wid >> 2, wn = wid & 3;

    wmma::fragment<wmma::accumulator, 16, 16, 16, float> acc[4][2];
    #pragma unroll
    for (int i = 0; i < 4; i++)
        #pragma unroll
        for (int j = 0; j < 2; j++) wmma::fill_fragment(acc[i][j], 0.f);

    int tiles = K / GBK;

    auto load_stage = [&](int t, int buf) {
        int k0 = t * GBK;
        #pragma unroll
        for (int r = 0; r < 2; r++) {
            int idx = threadIdx.x + r * 256;
            int row = idx >> 2, cg = idx & 3;
            cp16(&As[buf][row * AS_LD + cg * 8],
                 &A[(size_t)(bm + row) * K + k0 + cg * 8]);
        }
        #pragma unroll
        for (int r = 0; r < 2; r++) {
            int idx = threadIdx.x + r * 256;
            int row = idx >> 4, cg = idx & 15;
            cp16(&Bs[buf][row * BS_LD + cg * 8],
                 &Bm[(size_t)(k0 + row) * N + bn + cg * 8]);
        }
    };

    load_stage(0, 0); cp_commit();
    if (tiles > 1) { load_stage(1, 1); }
    cp_commit();

    for (int t = 0; t < tiles; t++) {
        int cur = t % NSTAGE;
        if (t + 2 < tiles) load_stage(t + 2, (t + 2) % NSTAGE);
        cp_commit();
        cp_wait2();
        __syncthreads();

        #pragma unroll
        for (int kk = 0; kk < GBK; kk += 16) {
            wmma::fragment<wmma::matrix_a, 16, 16, 16, __half, wmma::row_major> af[4];
            wmma::fragment<wmma::matrix_b, 16, 16, 16, __half, wmma::row_major> bf[2];
            #pragma unroll
            for (int i = 0; i < 4; i++)
                wmma::load_matrix_sync(af[i], &As[cur][(wm * 64 + i * 16) * AS_LD + kk], AS_LD);
            #pragma unroll
            for (int j = 0; j < 2; j++)
                wmma::load_matrix_sync(bf[j], &Bs[cur][kk * BS_LD + wn * 32 + j * 16], BS_LD);
            #pragma unroll
            for (int i = 0; i < 4; i++)
                #pragma unroll
                for (int j = 0; j < 2; j++)
                    wmma::mma_sync(acc[i][j], af[i], bf[j], acc[i][j]);
        }
        __syncthreads();
    }
    #pragma unroll
    for (int i = 0; i < 4; i++)
        #pragma unroll
        for (int j = 0; j < 2; j++)
            wmma::store_matrix_sync(&C[(size_t)(bm + wm * 64 + i * 16) * N + bn + wn * 32 + j * 16],
                                    acc[i][j], N, wmma::mem_row_major);
}

// ---------------- causal depthwise conv (K=4) + SiLU ----------------
__global__ void conv_silu_kernel(const float* __restrict__ cw) {
    int idx = blockIdx.x * blockDim.x + threadIdx.x;
    if (idx >= MR * EI) return;
    int e = idx & (EI - 1);
    int m = idx >> 11;
    int t = m & (L_SZ - 1);
    float w0 = cw[e * 4 + 0], w1 = cw[e * 4 + 1], w2 = cw[e * 4 + 2], w3 = cw[e * 4 + 3];
    float acc = w3 * g_xz[(size_t)m * (2 * EI) + e];
    if (t >= 1) acc += w2 * g_xz[(size_t)(m - 1) * (2 * EI) + e];
    if (t >= 2) acc += w1 * g_xz[(size_t)(m - 2) * (2 * EI) + e];
    if (t >= 3) acc += w0 * g_xz[(size_t)(m - 3) * (2 * EI) + e];
    float s = acc / (1.f + __expf(-acc));
    g_xact[idx] = s;
}

// ---------------- x_db = x_act(4096x2048) @ W_x(2048x96), fp32 SIMT ----------------
__global__ void __launch_bounds__(256) gemm_xdb_kernel(const float* __restrict__ Wx) {
    __shared__ float As[32 * 65];
    __shared__ float Ws[64 * 96];
    int m0 = blockIdx.x * 32;
    int r  = threadIdx.x & 31;
    int cg = threadIdx.x >> 5;
    float acc[12];
    #pragma unroll
    for (int j = 0; j < 12; j++) acc[j] = 0.f;

    for (int k0 = 0; k0 < EI; k0 += 64) {
        #pragma unroll
        for (int i = 0; i < 2; i++) {
            int idx = threadIdx.x + i * 256;
            int row = idx >> 4, c = (idx & 15) * 4;
            float4 v = *(const float4*)&g_xact[(size_t)(m0 + row) * EI + k0 + c];
            As[row * 65 + c] = v.x; As[row * 65 + c + 1] = v.y;
            As[row * 65 + c + 2] = v.z; As[row * 65 + c + 3] = v.w;
        }
        #pragma unroll
        for (int i = 0; i < 6; i++) {
            int idx = threadIdx.x + i * 256;
            int row = idx / 24, c = (idx % 24) * 4;
            *(float4*)&Ws[row * 96 + c] = *(const float4*)&Wx[(size_t)(k0 + row) * 96 + c];
        }
        __syncthreads();
        #pragma unroll 8
        for (int k = 0; k < 64; k++) {
            float a = As[r * 65 + k];
            #pragma unroll
            for (int j = 0; j < 12; j++)
                acc[j] = fmaf(a, Ws[k * 96 + cg * 12 + j], acc[j]);
        }
        __syncthreads();
    }
    #pragma unroll
    for (int j = 0; j < 12; j++)
        g_xdb[(size_t)(m0 + r) * 96 + cg * 12 + j] = acc[j];
}

// ---------------- delta = softplus(dt_lr(4096x64) @ W_dt(64x2048) + b_dt) ----------------
__global__ void __launch_bounds__(256) delta_kernel(const float* __restrict__ Wdt,
                                                    const float* __restrict__ bdt) {
    __shared__ float sdt[16 * 64];
    int m0 = (blockIdx.x >> 3) * 16;
    int c0 = (blockIdx.x & 7) * 256;
    for (int i = threadIdx.x; i < 16 * 64; i += 256) {
        int rr = i >> 6, kk = i & 63;
        sdt[i] = g_xdb[(size_t)(m0 + rr) * 96 + kk];
    }
    __syncthreads();
    int c = c0 + threadIdx.x;
    float acc[16];
    #pragma unroll
    for (int r = 0; r < 16; r++) acc[r] = 0.f;
    #pragma unroll 4
    for (int k = 0; k < 64; k++) {
        float w = Wdt[(size_t)k * EI + c];
        #pragma unroll
        for (int r = 0; r < 16; r++)
            acc[r] = fmaf(sdt[r * 64 + k], w, acc[r]);
    }
    float bb = bdt[c];
    #pragma unroll
    for (int r = 0; r < 16; r++) {
        float v = acc[r] + bb;
        float sp = (v > 20.f) ? v : log1pf(__expf(v));
        g_delta[(size_t)(m0 + r) * EI + c] = sp;
    }
}

// ---------------- selective scan, smem-staged chunks + fused gate ----------------
// Block = 32 channels of one batch, 128 threads (4 lanes/channel, 4 states/lane).
// Per chunk of 32 timesteps: cooperative cp.async bulk load of d/u/z/B/C into
// shared (double-buffered), then recurrence reads from shared with depth-1
// register prefetch. Converts per-step latency-bound gmem loads into
// bandwidth-bound bulk transfers.
#define TCH 32
#define NCH (L_SZ / TCH)

__global__ void __launch_bounds__(128) scan_kernel(const float* __restrict__ A_log,
                                                   const float* __restrict__ Dp,
                                                   float* __restrict__ hlast_out) {
    __shared__ __align__(16) float sd [2][TCH][32];
    __shared__ __align__(16) float su [2][TCH][32];
    __shared__ __align__(16) float sz [2][TCH][32];
    __shared__ __align__(16) float sbc[2][TCH][32];   // [B(16) | C(16)] per t

    int b  = blockIdx.x >> 6;                 // grid 256 = 4 batches * 64 groups
    int e0 = (blockIdx.x & 63) * 32;
    int tid  = threadIdx.x;
    int lane = tid & 31;
    int w    = tid >> 5;
    int ch   = w * 8 + (lane >> 2);           // 8 channels per warp
    int e    = e0 + ch;
    int q    = (lane & 3) * 4;                // state offset 0/4/8/12
    bool wlane = ((lane & 3) == 0);

    float Aa[4], h[4];
    #pragma unroll
    for (int j = 0; j < 4; j++) {
        Aa[j] = -__expf(A_log[e * NS + q + j]);
        h[j] = 0.f;
    }
    float Dpar = Dp[e];
    int mbase = b * L_SZ;

    // cooperative chunk loader: 2 slots per thread per array (256 cp16 rows-of-4)
    auto load_chunk = [&](int c, int buf) {
        int m0 = mbase + c * TCH;
        #pragma unroll
        for (int r = 0; r < 2; r++) {
            int slot = tid + r * 128;          // 0..255
            int t  = slot >> 3;                // 0..31
            int f4 = (slot & 7) * 4;           // float offset 0,4,..,28
            size_t m = (size_t)(m0 + t);
            cp16(&sd [buf][t][f4], &g_delta[m * EI + e0 + f4]);
            cp16(&su [buf][t][f4], &g_xact [m * EI + e0 + f4]);
            cp16(&sz [buf][t][f4], &g_xz   [m * (2 * EI) + EI + e0 + f4]);
            cp16(&sbc[buf][t][f4], &g_xdb  [m * 96 + 64 + f4]);
        }
    };

    load_chunk(0, 0);
    cp_commit();

    for (int c = 0; c < NCH; c++) {
        int buf = c & 1;
        if (c + 1 < NCH) load_chunk(c + 1, (c + 1) & 1);
        cp_commit();
        cp_wait1();            // chunk c resident (only chunk c+1's group pending)
        __syncthreads();

        float  d0 = sd[buf][0][ch];
        float  u0 = su[buf][0][ch];
        float  z0 = sz[buf][0][ch];
        float4 B0 = *(const float4*)&sbc[buf][0][q];
        float4 C0 = *(const float4*)&sbc[buf][0][16 + q];

        size_t mrow = (size_t)(mbase + c * TCH);
        #pragma unroll 4
        for (int t = 0; t < TCH; t++) {
            float d1 = 0.f, u1 = 0.f, z1 = 0.f; float4 B1 = B0, C1 = C0;
            if (t + 1 < TCH) {
                d1 = sd[buf][t + 1][ch];
                u1 = su[buf][t + 1][ch];
                z1 = sz[buf][t + 1][ch];
                B1 = *(const float4*)&sbc[buf][t + 1][q];
                C1 = *(const float4*)&sbc[buf][t + 1][16 + q];
            }
            float du = d0 * u0;
            float dA0 = __expf(d0 * Aa[0]);
            float dA1 = __expf(d0 * Aa[1]);
            float dA2 = __expf(d0 * Aa[2]);
            float dA3 = __expf(d0 * Aa[3]);
            h[0] = fmaf(dA0, h[0], du * B0.x);
            h[1] = fmaf(dA1, h[1], du * B0.y);
            h[2] = fmaf(dA2, h[2], du * B0.z);
            h[3] = fmaf(dA3, h[3], du * B0.w);
            float yp = h[0]*C0.x + h[1]*C0.y + h[2]*C0.z + h[3]*C0.w;
            yp += __shfl_xor_sync(~0u, yp, 1);
            yp += __shfl_xor_sync(~0u, yp, 2);
            if (wlane) {
                float zg = z0 / (1.f + __expf(-z0));     // silu(z)
                g_ygH[(mrow + t) * EI + e] =
                    __float2half((yp + u0 * Dpar) * zg);
            }
            d0 = d1; u0 = u1; z0 = z1; B0 = B1; C0 = C1;
        }
        __syncthreads();       // done with buf before chunk c+2 overwrites it
    }
    *(float4*)&hlast_out[((size_t)b * EI + e) * NS + q] = make_float4(h[0], h[1], h[2], h[3]);
}

// ---------------- residual add ----------------
__global__ void resadd_kernel(const float* __restrict__ hs, float* __restrict__ out) {
    int i = blockIdx.x * blockDim.x + threadIdx.x;
    if (i < MR * DM) out[i] = g_outtmp[i] + hs[i];
}

// ---------------- launch ----------------
extern "C" void kernel_launch(void* const* d_in, const int* in_sizes, int n_in,
                              void* d_out, int out_size) {
    const float* hs     = (const float*)d_in[0];
    const float* norm_w = (const float*)d_in[1];
    const float* W_in   = (const float*)d_in[2];
    const float* conv_w = (const float*)d_in[3];
    const float* W_x    = (const float*)d_in[4];
    const float* W_dt   = (const float*)d_in[5];
    const float* b_dt   = (const float*)d_in[6];
    const float* A_log  = (const float*)d_in[7];
    const float* D_par  = (const float*)d_in[8];
    const float* W_out  = (const float*)d_in[9];
    float* out   = (float*)d_out;
    float* hlast = out + (size_t)MR * DM;

    void *p_xh, *p_WinH, *p_WoutH, *p_xz, *p_ygH, *p_outtmp;
    cudaGetSymbolAddress(&p_xh, g_xh);
    cudaGetSymbolAddress(&p_WinH, g_WinH);
    cudaGetSymbolAddress(&p_WoutH, g_WoutH);
    cudaGetSymbolAddress(&p_xz, g_xz);
    cudaGetSymbolAddress(&p_ygH, g_ygH);
    cudaGetSymbolAddress(&p_outtmp, g_outtmp);

    rmsnorm_kernel<<<MR, 256>>>(hs, norm_w);
    {
        int n2 = DM * 2 * EI / 2;
        f2h_kernel<<<(n2 + 255) / 256, 256>>>(W_in, (__half*)p_WinH, n2);
    }
    {
        int n2 = EI * DM / 2;
        f2h_kernel<<<(n2 + 255) / 256, 256>>>(W_out, (__half*)p_WoutH, n2);
    }
    // xz = x @ W_in : M=4096, N=4096, K=1024
    gemm_h_kernel<<<dim3(2 * EI / GBN, MR / GBM), 256>>>(
        (const __half*)p_xh, (const __half*)p_WinH, (float*)p_xz, MR, 2 * EI, DM);
    conv_silu_kernel<<<MR * EI / 256, 256>>>(conv_w);
    gemm_xdb_kernel<<<MR / 32, 256>>>(W_x);
    delta_kernel<<<(MR / 16) * (EI / 256), 256>>>(W_dt, b_dt);
    scan_kernel<<<256, 128>>>(A_log, D_par, hlast);
    // out_tmp = y_g @ W_out : M=4096, N=1024, K=2048
    gemm_h_kernel<<<dim3(DM / GBN, MR / GBM), 256>>>(
        (const __half*)p_ygH, (const __half*)p_WoutH, (float*)p_outtmp, MR, DM, EI);
    resadd_kernel<<<MR * DM / 256, 256>>>(hs, out);
}

// round 13
// speedup vs baseline: 2.0144x; 1.1090x over previous
#include <cuda_runtime.h>
#include <cuda_fp16.h>
#include <cstdint>
#include <mma.h>
using namespace nvcuda;

#define B_SZ    4
#define L_SZ    1024
#define DM      1024
#define EI      2048
#define NS      16
#define DTR     64
#define MR      (B_SZ * L_SZ)          // 4096 token rows

// ---------------- scratch (static device globals; no allocation) ----------------
__device__ __half g_xh   [MR * DM];        // rmsnorm output, fp16
__device__ __half g_WinH [DM * 2 * EI];    // W_in fp16
__device__ __half g_WoutH[EI * DM];        // W_out fp16
__device__ __half g_WxH  [EI * 96];        // W_x fp16
__device__ float  g_xz   [MR * 2 * EI];    // in-proj output (x_in | z)
__device__ float  g_xact [MR * EI];        // silu(conv(x_in)) fp32 (scan u)
__device__ __half g_xactH[MR * EI];        // hi half of x_act
__device__ __half g_xactL[MR * EI];        // lo half: fp16(x - hi)
__device__ float  g_xdb  [MR * 96];        // [dt(64) | B(16) | C(16)]
__device__ float  g_delta[MR * EI];        // softplus(dt@W_dt + b_dt)
__device__ __half g_ygH  [MR * EI];        // y * silu(z), fp16
__device__ float  g_outtmp[MR * DM];       // y_g @ W_out

// ---------------- rmsnorm -> fp16 ----------------
__global__ void rmsnorm_kernel(const float* __restrict__ hs,
                               const float* __restrict__ w) {
    int row = blockIdx.x;
    const float4* hrow = (const float4*)(hs + (size_t)row * DM);
    float4 v = hrow[threadIdx.x];
    float ss = v.x*v.x + v.y*v.y + v.z*v.z + v.w*v.w;
    #pragma unroll
    for (int o = 16; o; o >>= 1) ss += __shfl_xor_sync(~0u, ss, o);
    __shared__ float sred[8];
    int warp = threadIdx.x >> 5, lane = threadIdx.x & 31;
    if (lane == 0) sred[warp] = ss;
    __syncthreads();
    if (warp == 0) {
        float s = lane < 8 ? sred[lane] : 0.f;
        #pragma unroll
        for (int o = 4; o; o >>= 1) s += __shfl_xor_sync(~0u, s, o);
        if (lane == 0) sred[0] = rsqrtf(s / (float)DM + 1e-6f);
    }
    __syncthreads();
    float sc = sred[0];
    float4 wl = ((const float4*)w)[threadIdx.x];
    __half2* out = (__half2*)(g_xh + (size_t)row * DM);
    out[threadIdx.x * 2]     = __floats2half2_rn(v.x * sc * wl.x, v.y * sc * wl.y);
    out[threadIdx.x * 2 + 1] = __floats2half2_rn(v.z * sc * wl.z, v.w * sc * wl.w);
}

// ---------------- f32 -> f16 convert ----------------
__global__ void f2h_kernel(const float* __restrict__ src, __half* __restrict__ dst, int n2) {
    int i = blockIdx.x * blockDim.x + threadIdx.x;
    if (i < n2) {
        float2 v = ((const float2*)src)[i];
        ((__half2*)dst)[i] = __floats2half2_rn(v.x, v.y);
    }
}

// ---------------- cp.async helpers ----------------
__device__ __forceinline__ void cp16(void* s, const void* g) {
    unsigned int sa = (unsigned int)__cvta_generic_to_shared(s);
    asm volatile("cp.async.cg.shared.global [%0], [%1], 16;\n" :: "r"(sa), "l"(g));
}
__device__ __forceinline__ void cp_commit() {
    asm volatile("cp.async.commit_group;\n" ::: "memory");
}
__device__ __forceinline__ void cp_wait1() {
    asm volatile("cp.async.wait_group 1;\n" ::: "memory");
}
__device__ __forceinline__ void cp_wait2() {
    asm volatile("cp.async.wait_group 2;\n" ::: "memory");
}

// ---------------- fp16 WMMA GEMM, 3-stage cp.async pipeline ----------------
#define GBM 128
#define GBN 128
#define GBK 32
#define NSTAGE 3
#define AS_LD 40
#define BS_LD 136

__global__ void __launch_bounds__(256) gemm_h_kernel(const __half* __restrict__ A,
                                                     const __half* __restrict__ Bm,
                                                     float* __restrict__ C,
                                                     int M, int N, int K) {
    __shared__ __half As[NSTAGE][GBM * AS_LD];
    __shared__ __half Bs[NSTAGE][GBK * BS_LD];
    int bm = blockIdx.y * GBM, bn = blockIdx.x * GBN;
    int wid = threadIdx.x >> 5;
    int wm = wid >> 2, wn = wid & 3;

    wmma::fragment<wmma::accumulator, 16, 16, 16, float> acc[4][2];
    #pragma unroll
    for (int i = 0; i < 4; i++)
        #pragma unroll
        for (int j = 0; j < 2; j++) wmma::fill_fragment(acc[i][j], 0.f);

    int tiles = K / GBK;

    auto load_stage = [&](int t, int buf) {
        int k0 = t * GBK;
        #pragma unroll
        for (int r = 0; r < 2; r++) {
            int idx = threadIdx.x + r * 256;
            int row = idx >> 2, cg = idx & 3;
            cp16(&As[buf][row * AS_LD + cg * 8],
                 &A[(size_t)(bm + row) * K + k0 + cg * 8]);
        }
        #pragma unroll
        for (int r = 0; r < 2; r++) {
            int idx = threadIdx.x + r * 256;
            int row = idx >> 4, cg = idx & 15;
            cp16(&Bs[buf][row * BS_LD + cg * 8],
                 &Bm[(size_t)(k0 + row) * N + bn + cg * 8]);
        }
    };

    load_stage(0, 0); cp_commit();
    if (tiles > 1) { load_stage(1, 1); }
    cp_commit();

    for (int t = 0; t < tiles; t++) {
        int cur = t % NSTAGE;
        if (t + 2 < tiles) load_stage(t + 2, (t + 2) % NSTAGE);
        cp_commit();
        cp_wait2();
        __syncthreads();

        #pragma unroll
        for (int kk = 0; kk < GBK; kk += 16) {
            wmma::fragment<wmma::matrix_a, 16, 16, 16, __half, wmma::row_major> af[4];
            wmma::fragment<wmma::matrix_b, 16, 16, 16, __half, wmma::row_major> bf[2];
            #pragma unroll
            for (int i = 0; i < 4; i++)
                wmma::load_matrix_sync(af[i], &As[cur][(wm * 64 + i * 16) * AS_LD + kk], AS_LD);
            #pragma unroll
            for (int j = 0; j < 2; j++)
                wmma::load_matrix_sync(bf[j], &Bs[cur][kk * BS_LD + wn * 32 + j * 16], BS_LD);
            #pragma unroll
            for (int i = 0; i < 4; i++)
                #pragma unroll
                for (int j = 0; j < 2; j++)
                    wmma::mma_sync(acc[i][j], af[i], bf[j], acc[i][j]);
        }
        __syncthreads();
    }
    #pragma unroll
    for (int i = 0; i < 4; i++)
        #pragma unroll
        for (int j = 0; j < 2; j++)
            wmma::store_matrix_sync(&C[(size_t)(bm + wm * 64 + i * 16) * N + bn + wn * 32 + j * 16],
                                    acc[i][j], N, wmma::mem_row_major);
}

// ---------------- causal dwconv (K=4) + SiLU, 4 timesteps/thread, hi/lo emit ----------------
__global__ void conv_silu_kernel(const float* __restrict__ cw) {
    int i4 = blockIdx.x * blockDim.x + threadIdx.x;   // MR*EI/4 total
    if (i4 >= MR * EI / 4) return;
    int e  = i4 & (EI - 1);
    int g  = i4 >> 11;            // row-group 0..1023
    int m0 = g * 4;
    int t0 = m0 & (L_SZ - 1);
    float w0 = cw[e * 4 + 0], w1 = cw[e * 4 + 1], w2 = cw[e * 4 + 2], w3 = cw[e * 4 + 3];
    float xb[7];
    #pragma unroll
    for (int j = 0; j < 7; j++) {
        int tj = t0 - 3 + j;
        xb[j] = (tj >= 0) ? g_xz[(size_t)(m0 - 3 + j) * (2 * EI) + e] : 0.f;
    }
    #pragma unroll
    for (int s = 0; s < 4; s++) {
        float acc = w0 * xb[s] + w1 * xb[s + 1] + w2 * xb[s + 2] + w3 * xb[s + 3];
        float v = acc / (1.f + __expf(-acc));
        size_t o = (size_t)(m0 + s) * EI + e;
        g_xact[o] = v;
        __half hi = __float2half(v);
        g_xactH[o] = hi;
        g_xactL[o] = __float2half(v - __half2float(hi));
    }
}

// ---------------- x_db via fp16 WMMA with hi/lo compensation ----------------
// x_db(4096x96) = (xH + xL)(4096x2048) @ W_x(2048x96), fp32 accumulate.
#define XBM 128
#define XBN 96
#define XBK 32
#define XA_LD 40
#define XB_LD 104

__global__ void __launch_bounds__(256) gemm_xdb_h_kernel() {
    __shared__ __half Ah[2][XBM * XA_LD];
    __shared__ __half Al[2][XBM * XA_LD];
    __shared__ __half Bsx[2][XBK * XB_LD];
    int bm = blockIdx.x * XBM;
    int tid = threadIdx.x;
    int wid = tid >> 5;
    int wm = wid >> 1, wn = wid & 1;     // 4x2 warp grid, warp tile 32x48

    wmma::fragment<wmma::accumulator, 16, 16, 16, float> acc[2][3];
    #pragma unroll
    for (int i = 0; i < 2; i++)
        #pragma unroll
        for (int j = 0; j < 3; j++) wmma::fill_fragment(acc[i][j], 0.f);

    const int tiles = EI / XBK;          // 64

    auto load_stage = [&](int t, int buf) {
        int k0 = t * XBK;
        #pragma unroll
        for (int r = 0; r < 2; r++) {    // A hi/lo: 128x32 halves = 512 uint4 each
            int idx = tid + r * 256;
            int row = idx >> 2, cg = idx & 3;
            cp16(&Ah[buf][row * XA_LD + cg * 8],
                 &g_xactH[(size_t)(bm + row) * EI + k0 + cg * 8]);
            cp16(&Al[buf][row * XA_LD + cg * 8],
                 &g_xactL[(size_t)(bm + row) * EI + k0 + cg * 8]);
        }
        for (int i = tid; i < 384; i += 256) {   // B: 32x96 halves = 384 uint4
            int row = i / 12, cg = i % 12;
            cp16(&Bsx[buf][row * XB_LD + cg * 8],
                 &g_WxH[(size_t)(k0 + row) * 96 + cg * 8]);
        }
    };

    load_stage(0, 0);
    cp_commit();

    for (int t = 0; t < tiles; t++) {
        int cur = t & 1;
        if (t + 1 < tiles) load_stage(t + 1, (t + 1) & 1);
        cp_commit();
        cp_wait1();
        __syncthreads();

        #pragma unroll
        for (int kk = 0; kk < XBK; kk += 16) {
            wmma::fragment<wmma::matrix_a, 16, 16, 16, __half, wmma::row_major> afh[2], afl[2];
            wmma::fragment<wmma::matrix_b, 16, 16, 16, __half, wmma::row_major> bf[3];
            #pragma unroll
            for (int i = 0; i < 2; i++) {
                wmma::load_matrix_sync(afh[i], &Ah[cur][(wm * 32 + i * 16) * XA_LD + kk], XA_LD);
                wmma::load_matrix_sync(afl[i], &Al[cur][(wm * 32 + i * 16) * XA_LD + kk], XA_LD);
            }
            #pragma unroll
            for (int j = 0; j < 3; j++)
                wmma::load_matrix_sync(bf[j], &Bsx[cur][kk * XB_LD + wn * 48 + j * 16], XB_LD);
            #pragma unroll
            for (int i = 0; i < 2; i++)
                #pragma unroll
                for (int j = 0; j < 3; j++) {
                    wmma::mma_sync(acc[i][j], afh[i], bf[j], acc[i][j]);
                    wmma::mma_sync(acc[i][j], afl[i], bf[j], acc[i][j]);
                }
        }
        __syncthreads();
    }
    #pragma unroll
    for (int i = 0; i < 2; i++)
        #pragma unroll
        for (int j = 0; j < 3; j++)
            wmma::store_matrix_sync(&g_xdb[(size_t)(bm + wm * 32 + i * 16) * 96 + wn * 48 + j * 16],
                                    acc[i][j], 96, wmma::mem_row_major);
}

// ---------------- delta = softplus(dt_lr(4096x64) @ W_dt(64x2048) + b_dt) ----------------
__global__ void __launch_bounds__(256) delta_kernel(const float* __restrict__ Wdt,
                                                    const float* __restrict__ bdt) {
    __shared__ float sdt[16 * 64];
    int m0 = (blockIdx.x >> 3) * 16;
    int c0 = (blockIdx.x & 7) * 256;
    for (int i = threadIdx.x; i < 16 * 64; i += 256) {
        int rr = i >> 6, kk = i & 63;
        sdt[i] = g_xdb[(size_t)(m0 + rr) * 96 + kk];
    }
    __syncthreads();
    int c = c0 + threadIdx.x;
    float acc[16];
    #pragma unroll
    for (int r = 0; r < 16; r++) acc[r] = 0.f;
    #pragma unroll 4
    for (int k = 0; k < 64; k++) {
        float w = Wdt[(size_t)k * EI + c];
        #pragma unroll
        for (int r = 0; r < 16; r++)
            acc[r] = fmaf(sdt[r * 64 + k], w, acc[r]);
    }
    float bb = bdt[c];
    #pragma unroll
    for (int r = 0; r < 16; r++) {
        float v = acc[r] + bb;
        float sp = (v > 20.f) ? v : log1pf(__expf(v));
        g_delta[(size_t)(m0 + r) * EI + c] = sp;
    }
}

// ---------------- selective scan, smem-staged chunks + fused gate ----------------
#define TCH 32
#define NCH (L_SZ / TCH)

__global__ void __launch_bounds__(128) scan_kernel(const float* __restrict__ A_log,
                                                   const float* __restrict__ Dp,
                                                   float* __restrict__ hlast_out) {
    __shared__ __align__(16) float sd [2][TCH][32];
    __shared__ __align__(16) float su [2][TCH][32];
    __shared__ __align__(16) float sz [2][TCH][32];
    __shared__ __align__(16) float sbc[2][TCH][32];

    int b  = blockIdx.x >> 6;
    int e0 = (blockIdx.x & 63) * 32;
    int tid  = threadIdx.x;
    int lane = tid & 31;
    int w    = tid >> 5;
    int ch   = w * 8 + (lane >> 2);
    int e    = e0 + ch;
    int q    = (lane & 3) * 4;
    bool wlane = ((lane & 3) == 0);

    float Aa[4], h[4];
    #pragma unroll
    for (int j = 0; j < 4; j++) {
        Aa[j] = -__expf(A_log[e * NS + q + j]);
        h[j] = 0.f;
    }
    float Dpar = Dp[e];
    int mbase = b * L_SZ;

    auto load_chunk = [&](int c, int buf) {
        int m0 = mbase + c * TCH;
        #pragma unroll
        for (int r = 0; r < 2; r++) {
            int slot = tid + r * 128;
            int t  = slot >> 3;
            int f4 = (slot & 7) * 4;
            size_t m = (size_t)(m0 + t);
            cp16(&sd [buf][t][f4], &g_delta[m * EI + e0 + f4]);
            cp16(&su [buf][t][f4], &g_xact [m * EI + e0 + f4]);
            cp16(&sz [buf][t][f4], &g_xz   [m * (2 * EI) + EI + e0 + f4]);
            cp16(&sbc[buf][t][f4], &g_xdb  [m * 96 + 64 + f4]);
        }
    };

    load_chunk(0, 0);
    cp_commit();

    for (int c = 0; c < NCH; c++) {
        int buf = c & 1;
        if (c + 1 < NCH) load_chunk(c + 1, (c + 1) & 1);
        cp_commit();
        cp_wait1();
        __syncthreads();

        float  d0 = sd[buf][0][ch];
        float  u0 = su[buf][0][ch];
        float  z0 = sz[buf][0][ch];
        float4 B0 = *(const float4*)&sbc[buf][0][q];
        float4 C0 = *(const float4*)&sbc[buf][0][16 + q];

        size_t mrow = (size_t)(mbase + c * TCH);
        #pragma unroll 4
        for (int t = 0; t < TCH; t++) {
            float d1 = 0.f, u1 = 0.f, z1 = 0.f; float4 B1 = B0, C1 = C0;
            if (t + 1 < TCH) {
                d1 = sd[buf][t + 1][ch];
                u1 = su[buf][t + 1][ch];
                z1 = sz[buf][t + 1][ch];
                B1 = *(const float4*)&sbc[buf][t + 1][q];
                C1 = *(const float4*)&sbc[buf][t + 1][16 + q];
            }
            float du = d0 * u0;
            float dA0 = __expf(d0 * Aa[0]);
            float dA1 = __expf(d0 * Aa[1]);
            float dA2 = __expf(d0 * Aa[2]);
            float dA3 = __expf(d0 * Aa[3]);
            h[0] = fmaf(dA0, h[0], du * B0.x);
            h[1] = fmaf(dA1, h[1], du * B0.y);
            h[2] = fmaf(dA2, h[2], du * B0.z);
            h[3] = fmaf(dA3, h[3], du * B0.w);
            float yp = h[0]*C0.x + h[1]*C0.y + h[2]*C0.z + h[3]*C0.w;
            yp += __shfl_xor_sync(~0u, yp, 1);
            yp += __shfl_xor_sync(~0u, yp, 2);
            if (wlane) {
                float zg = z0 / (1.f + __expf(-z0));
                g_ygH[(mrow + t) * EI + e] =
                    __float2half((yp + u0 * Dpar) * zg);
            }
            d0 = d1; u0 = u1; z0 = z1; B0 = B1; C0 = C1;
        }
        __syncthreads();
    }
    *(float4*)&hlast_out[((size_t)b * EI + e) * NS + q] = make_float4(h[0], h[1], h[2], h[3]);
}

// ---------------- residual add ----------------
__global__ void resadd_kernel(const float* __restrict__ hs, float* __restrict__ out) {
    int i = blockIdx.x * blockDim.x + threadIdx.x;
    if (i < MR * DM) out[i] = g_outtmp[i] + hs[i];
}

// ---------------- launch ----------------
extern "C" void kernel_launch(void* const* d_in, const int* in_sizes, int n_in,
                              void* d_out, int out_size) {
    const float* hs     = (const float*)d_in[0];
    const float* norm_w = (const float*)d_in[1];
    const float* W_in   = (const float*)d_in[2];
    const float* conv_w = (const float*)d_in[3];
    const float* W_x    = (const float*)d_in[4];
    const float* W_dt   = (const float*)d_in[5];
    const float* b_dt   = (const float*)d_in[6];
    const float* A_log  = (const float*)d_in[7];
    const float* D_par  = (const float*)d_in[8];
    const float* W_out  = (const float*)d_in[9];
    float* out   = (float*)d_out;
    float* hlast = out + (size_t)MR * DM;

    void *p_xh, *p_WinH, *p_WoutH, *p_WxH, *p_xz, *p_ygH, *p_outtmp;
    cudaGetSymbolAddress(&p_xh, g_xh);
    cudaGetSymbolAddress(&p_WinH, g_WinH);
    cudaGetSymbolAddress(&p_WoutH, g_WoutH);
    cudaGetSymbolAddress(&p_WxH, g_WxH);
    cudaGetSymbolAddress(&p_xz, g_xz);
    cudaGetSymbolAddress(&p_ygH, g_ygH);
    cudaGetSymbolAddress(&p_outtmp, g_outtmp);

    rmsnorm_kernel<<<MR, 256>>>(hs, norm_w);
    {
        int n2 = DM * 2 * EI / 2;
        f2h_kernel<<<(n2 + 255) / 256, 256>>>(W_in, (__half*)p_WinH, n2);
    }
    {
        int n2 = EI * DM / 2;
        f2h_kernel<<<(n2 + 255) / 256, 256>>>(W_out, (__half*)p_WoutH, n2);
    }
    {
        int n2 = EI * 96 / 2;
        f2h_kernel<<<(n2 + 255) / 256, 256>>>(W_x, (__half*)p_WxH, n2);
    }
    // xz = x @ W_in : M=4096, N=4096, K=1024
    gemm_h_kernel<<<dim3(2 * EI / GBN, MR / GBM), 256>>>(
        (const __half*)p_xh, (const __half*)p_WinH, (float*)p_xz, MR, 2 * EI, DM);
    conv_silu_kernel<<<MR * EI / 4 / 256, 256>>>(conv_w);
    gemm_xdb_h_kernel<<<MR / XBM, 256>>>();
    delta_kernel<<<(MR / 16) * (EI / 256), 256>>>(W_dt, b_dt);
    scan_kernel<<<256, 128>>>(A_log, D_par, hlast);
    // out_tmp = y_g @ W_out : M=4096, N=1024, K=2048
    gemm_h_kernel<<<dim3(DM / GBN, MR / GBM), 256>>>(
        (const __half*)p_ygH, (const __half*)p_WoutH, (float*)p_outtmp, MR, DM, EI);
    resadd_kernel<<<MR * DM / 256, 256>>>(hs, out);
}